// round 13
// baseline (speedup 1.0000x reference)
#include <cuda_runtime.h>
#include <cuda_bf16.h>
#include <cstdint>

#define BB 2
#define NQ 256
#define ED 512
#define HH 150
#define HP 152

#define P1 272            // B1 pitch (bytes)
#define PH 304            // HtB/W2s pitch (bytes)
#define PG2 1040          // g staging pitch (bytes)

// ---------------- device scratch ----------------
__device__ __nv_bfloat16 d_w1ctb[HP*ED];      // W1c^T bf16 [h][e]
__device__ __nv_bfloat16 d_w2t[HP*HP];        // W2^T bf16 [o][k]
__device__ float         d_hip[2*BB*NQ*HP];   // hi+b1 partials
__device__ float         d_hjp[2*BB*NQ*HP];   // hj partials

// ---------------- smem layout (bytes) ----------------
#define SM_HIS  0                       // 9728
#define SM_HJS  9728                    // -> 19456
#define SM_B2S  19456                   // 608
#define SM_W3S  20064                   // 608
#define SM_MIS  20672                   // 64
#define SM_MJS  20736                   // 64
#define SM_U    20800
// stage-1: [G 33280][B0 41344][B1 41344]
#define OFF_G   0
#define OFF_B0  33280
#define OFF_B1b 74624
// stage-2 aliases
#define OFF_W2  0                       // 46208
#define OFF_HB  46208                   // 77824 -> 124032
#define SMEM_BYTES (SM_U + 124032)      // 144832

__device__ __forceinline__ uint32_t smem_u32(const void* p) {
    uint32_t a;
    asm("{ .reg .u64 t; cvta.to.shared.u64 t, %1; cvt.u32.u64 %0, t; }" : "=r"(a) : "l"(p));
    return a;
}
__device__ __forceinline__ void ldsm_x4(uint32_t& r0, uint32_t& r1, uint32_t& r2, uint32_t& r3,
                                        uint32_t addr) {
    asm volatile("ldmatrix.sync.aligned.m8n8.x4.shared.b16 {%0,%1,%2,%3}, [%4];"
                 : "=r"(r0), "=r"(r1), "=r"(r2), "=r"(r3) : "r"(addr));
}
__device__ __forceinline__ void ldsm_x2(uint32_t& r0, uint32_t& r1, uint32_t addr) {
    asm volatile("ldmatrix.sync.aligned.m8n8.x2.shared.b16 {%0,%1}, [%2];"
                 : "=r"(r0), "=r"(r1) : "r"(addr));
}
__device__ __forceinline__ void ldsm_x1(uint32_t& r0, uint32_t addr) {
    asm volatile("ldmatrix.sync.aligned.m8n8.x1.shared.b16 {%0}, [%1];"
                 : "=r"(r0) : "r"(addr));
}
__device__ __forceinline__ void mma16816(float* d, uint32_t a0, uint32_t a1, uint32_t a2,
                                         uint32_t a3, uint32_t b0, uint32_t b1) {
    asm volatile("mma.sync.aligned.m16n8k16.row.col.f32.bf16.bf16.f32 "
                 "{%0,%1,%2,%3}, {%4,%5,%6,%7}, {%8,%9}, {%0,%1,%2,%3};"
                 : "+f"(d[0]), "+f"(d[1]), "+f"(d[2]), "+f"(d[3])
                 : "r"(a0), "r"(a1), "r"(a2), "r"(a3), "r"(b0), "r"(b1));
}
__device__ __forceinline__ void mma16808(float* d, uint32_t a0, uint32_t a1, uint32_t b0) {
    asm volatile("mma.sync.aligned.m16n8k8.row.col.f32.bf16.bf16.f32 "
                 "{%0,%1,%2,%3}, {%4,%5}, {%6}, {%0,%1,%2,%3};"
                 : "+f"(d[0]), "+f"(d[1]), "+f"(d[2]), "+f"(d[3])
                 : "r"(a0), "r"(a1), "r"(b0));
}
__device__ __forceinline__ uint32_t mulbf2(uint32_t a, uint32_t b) {
    uint32_t r;
    asm("mul.bf16x2 %0, %1, %2;" : "=r"(r) : "r"(a), "r"(b));
    return r;
}
__device__ __forceinline__ float2 bf2_to_f2(uint32_t u) {
    __nv_bfloat162 h = *(__nv_bfloat162*)&u;
    return __bfloat1622float2(h);
}
__device__ __forceinline__ uint32_t pack_bf2(float x, float y) {
    __nv_bfloat162 p = __floats2bfloat162_rn(x, y);
    return *(uint32_t*)&p;
}

// ---------------- prekernels ----------------
__global__ void prep_w1ct(const float* __restrict__ W1) {
    __shared__ float tile[32][33];
    int e0 = blockIdx.x * 32, h0 = blockIdx.y * 32;
    int tx = threadIdx.x, ty = threadIdx.y;
    int h = h0 + tx, e = e0 + ty;
    tile[ty][tx] = (h < HH) ? W1[(size_t)(2*ED + e)*HH + h] : 0.f;
    __syncthreads();
    int ho = h0 + ty, eo = e0 + tx;
    if (ho < HP) d_w1ctb[ho*ED + eo] = __float2bfloat16(tile[tx][ty]);
}
__global__ void prep_w2t(const float* __restrict__ W2) {
    int o = blockIdx.x, k = threadIdx.x;
    float v = (o < HH && k < HH) ? W2[k*HH + o] : 0.f;
    d_w2t[o*HP + k] = __float2bfloat16(v);
}
__global__ void prep_hihj(const float* __restrict__ g, const float* __restrict__ W1,
                          const float* __restrict__ b1) {
    __shared__ float gs[8][256];
    __shared__ float red[4][8][160];
    const int n0 = blockIdx.x * 8, b = blockIdx.y, z = blockIdx.z;
    const int h = threadIdx.x, s = threadIdx.y;
    const int t = s*160 + h;
    for (int idx = t; idx < 8*256; idx += 640) {
        int row = idx >> 8, e = idx & 255;
        gs[row][e] = g[(size_t)(b*NQ + n0 + row)*ED + z*256 + e];
    }
    __syncthreads();
    float a1[8], a2[8];
    #pragma unroll
    for (int r = 0; r < 8; r++) { a1[r] = 0.f; a2[r] = 0.f; }
    if (h < HH) {
        const int ebase = z*256 + s*64;
        const float* pa = W1 + (size_t)ebase*HH + h;
        const float* pb = W1 + (size_t)(ED + ebase)*HH + h;
        const float* gp = &gs[0][s*64];
        #pragma unroll 4
        for (int el = 0; el < 64; el++) {
            float wa = pa[(size_t)el*HH];
            float wb = pb[(size_t)el*HH];
            #pragma unroll
            for (int r = 0; r < 8; r++) {
                float ge = gp[r*256 + el];
                a1[r] = fmaf(ge, wa, a1[r]);
                a2[r] = fmaf(ge, wb, a2[r]);
            }
        }
    }
    #pragma unroll
    for (int r = 0; r < 8; r++) red[s][r][h] = a1[r];
    __syncthreads();
    if (s == 0 && h < HP) {
        #pragma unroll
        for (int r = 0; r < 8; r++) {
            float v = 0.f;
            if (h < HH) {
                v = red[0][r][h] + red[1][r][h] + red[2][r][h] + red[3][r][h];
                if (z == 0) v += b1[h];
            }
            d_hip[z*(BB*NQ*HP) + (b*NQ + n0 + r)*HP + h] = v;
        }
    }
    __syncthreads();
    #pragma unroll
    for (int r = 0; r < 8; r++) red[s][r][h] = a2[r];
    __syncthreads();
    if (s == 0 && h < HP) {
        #pragma unroll
        for (int r = 0; r < 8; r++) {
            float v = 0.f;
            if (h < HH)
                v = red[0][r][h] + red[1][r][h] + red[2][r][h] + red[3][r][h];
            d_hjp[z*(BB*NQ*HP) + (b*NQ + n0 + r)*HP + h] = v;
        }
    }
}

// ---------------- main kernel: 256 thr, 8 warps x 2 m-tiles, shared B frags ----------------
__global__ __launch_bounds__(256, 1)
void pair_frag2_kernel(const float* __restrict__ g,
                       const float* __restrict__ m,
                       const float* __restrict__ b2,
                       const float* __restrict__ W3,
                       const float* __restrict__ b3,
                       float* __restrict__ out) {
    extern __shared__ char smc[];
    const int t = threadIdx.x, w = t >> 5, lane = t & 31;
    const int b = blockIdx.y;
    int I = 0, rem = blockIdx.x;
    while (rem >= 16 - I) { rem -= 16 - I; I++; }
    const int J = I + rem;
    const int i0 = I << 4, j0 = J << 4;
    const bool diag = (I == J);

    __nv_bfloat16* his = (__nv_bfloat16*)(smc + SM_HIS);
    __nv_bfloat16* hjs = (__nv_bfloat16*)(smc + SM_HJS);
    float* b2s = (float*)(smc + SM_B2S);
    float* w3s = (float*)(smc + SM_W3S);
    float* mIs = (float*)(smc + SM_MIS);
    float* mJs = (float*)(smc + SM_MJS);
    char* Gc  = smc + SM_U + OFF_G;
    char* Bp[2] = { smc + SM_U + OFF_B0, smc + SM_U + OFF_B1b };
    char* W2s = smc + SM_U + OFF_W2;
    char* HtB = smc + SM_U + OFF_HB;

    // ---- tables ----
    for (int idx = t; idx < 16*HP; idx += 256) {
        int r = idx / HP, h = idx - r*HP;
        int io = (b*NQ + i0 + r)*HP + h;
        int jo = (b*NQ + j0 + r)*HP + h;
        his[r*HP + h]        = __float2bfloat16(d_hip[io] + d_hip[BB*NQ*HP + io]);
        his[(16 + r)*HP + h] = __float2bfloat16(d_hip[jo] + d_hip[BB*NQ*HP + jo]);
        hjs[r*HP + h]        = __float2bfloat16(d_hjp[io] + d_hjp[BB*NQ*HP + io]);
        hjs[(16 + r)*HP + h] = __float2bfloat16(d_hjp[jo] + d_hjp[BB*NQ*HP + jo]);
    }
    for (int idx = t; idx < HP; idx += 256) {
        b2s[idx] = (idx < HH) ? b2[idx] : 0.f;
        w3s[idx] = (idx < HH) ? W3[idx] : 0.f;
    }
    if (t < 16)       mIs[t]      = m[b*NQ + i0 + t];
    else if (t < 32)  mJs[t - 16] = m[b*NQ + j0 + (t - 16)];

    // ---- stage g into G (32 rows x 512 bf16) ----
    {
        int r = t >> 3;
        int grow = (r < 16) ? (i0 + r) : (j0 + (r - 16));
        int c0 = (t & 7) * 64;
        const float* gp = g + (size_t)(b*NQ + grow)*ED + c0;
        char* dst = Gc + r*PG2 + c0*2;
        #pragma unroll
        for (int q = 0; q < 8; q++) {
            float4 va = *(const float4*)(gp + q*8);
            float4 vb = *(const float4*)(gp + q*8 + 4);
            uint4 v = { pack_bf2(va.x, va.y), pack_bf2(va.z, va.w),
                        pack_bf2(vb.x, vb.y), pack_bf2(vb.z, vb.w) };
            *(uint4*)(dst + q*16) = v;
        }
    }
    // ---- B(0) ----
    #pragma unroll
    for (int q = 0; q < 10; q++) {
        int idx = q*256 + t;
        if (idx < 2432) {
            int row = idx >> 4, c16 = idx & 15;
            *(uint4*)(Bp[0] + row*P1 + c16*16) = *(const uint4*)(d_w1ctb + row*ED + c16*8);
        }
    }
    __syncthreads();

    float acc[2][19][4];
    #pragma unroll
    for (int mt = 0; mt < 2; mt++)
        #pragma unroll
        for (int n = 0; n < 19; n++)
            #pragma unroll
            for (int k = 0; k < 4; k++) acc[mt][n][k] = 0.f;

    // A-fragment pointers: warp w covers i-rows {w, w+8}
    const char* gip0 = Gc + w*PG2 + (lane & 3)*4;
    const char* gip1 = Gc + (w + 8)*PG2 + (lane & 3)*4;
    const char* gjAp = Gc + (16 + (lane >> 2))*PG2 + (lane & 3)*4;
    const char* gjBp = gjAp + 8*PG2;
    const uint32_t brow  = (lane & 7) + ((lane >> 4) << 3);
    const uint32_t bkoff = ((lane >> 3) & 1) << 4;

    // ---- stage 1: 4 K-chunks, double-buffered B, register A-frags, shared B ----
    #pragma unroll
    for (int c = 0; c < 4; c++) {
        if (c < 3) {
            char* Bd = Bp[(c + 1) & 1];
            const __nv_bfloat16* bsrc = d_w1ctb + (c + 1)*128;
            #pragma unroll
            for (int q = 0; q < 10; q++) {
                int idx = q*256 + t;
                if (idx < 2432) {
                    int row = idx >> 4, c16 = idx & 15;
                    *(uint4*)(Bd + row*P1 + c16*16) = *(const uint4*)(bsrc + row*ED + c16*8);
                }
            }
        }
        const uint32_t Ba = smem_u32(Bp[c & 1]);
        #pragma unroll
        for (int ks = 0; ks < 8; ks++) {
            const int eb = c*256 + ks*32;
            uint32_t gi00 = *(const uint32_t*)(gip0 + eb);
            uint32_t gi01 = *(const uint32_t*)(gip0 + eb + 16);
            uint32_t gi10 = *(const uint32_t*)(gip1 + eb);
            uint32_t gi11 = *(const uint32_t*)(gip1 + eb + 16);
            uint32_t ga0  = *(const uint32_t*)(gjAp + eb);
            uint32_t ga1  = *(const uint32_t*)(gjAp + eb + 16);
            uint32_t gb0  = *(const uint32_t*)(gjBp + eb);
            uint32_t gb1  = *(const uint32_t*)(gjBp + eb + 16);
            uint32_t a00 = mulbf2(gi00, ga0), a01 = mulbf2(gi00, gb0);
            uint32_t a02 = mulbf2(gi01, ga1), a03 = mulbf2(gi01, gb1);
            uint32_t a10 = mulbf2(gi10, ga0), a11 = mulbf2(gi10, gb0);
            uint32_t a12 = mulbf2(gi11, ga1), a13 = mulbf2(gi11, gb1);
            uint32_t bb = Ba + brow*P1 + bkoff + ks*32;
            #pragma unroll
            for (int np = 0; np < 9; np++) {
                uint32_t b0, b1r, b2r, b3r;
                ldsm_x4(b0, b1r, b2r, b3r, bb + np*(16*P1));
                mma16816(acc[0][2*np],     a00, a01, a02, a03, b0, b1r);
                mma16816(acc[1][2*np],     a10, a11, a12, a13, b0, b1r);
                mma16816(acc[0][2*np + 1], a00, a01, a02, a03, b2r, b3r);
                mma16816(acc[1][2*np + 1], a10, a11, a12, a13, b2r, b3r);
            }
            uint32_t b0, b1r;
            ldsm_x2(b0, b1r, Ba + (144 + (lane & 7))*P1 + bkoff + ks*32);
            mma16816(acc[0][18], a00, a01, a02, a03, b0, b1r);
            mma16816(acc[1][18], a10, a11, a12, a13, b0, b1r);
        }
        __syncthreads();
    }

    // ---- epilogue 1: hA (both m-tiles) in regs; hB -> HtB; W2 -> W2s ----
    uint32_t hA[2][19][2];
    {
        #pragma unroll
        for (int q = 0; q < 12; q++) {
            int idx = q*256 + t;
            if (idx < HP*19) {
                int row = idx / 19, c16 = idx - row*19;
                *(uint4*)(W2s + row*PH + c16*16) = *(const uint4*)(d_w2t + row*HP + c16*8);
            }
        }
        const int jlo = lane >> 2, jhi = jlo + 8;
        const __nv_bfloat16* hjJl = hjs + (16 + jlo)*HP;
        const __nv_bfloat16* hjJh = hjs + (16 + jhi)*HP;
        const __nv_bfloat16* hiJl = his + (16 + jlo)*HP;
        const __nv_bfloat16* hiJh = his + (16 + jhi)*HP;
        #pragma unroll
        for (int mt = 0; mt < 2; mt++) {
            const int ii = w + mt*8;
            const __nv_bfloat16* hiIr = his + ii*HP;
            const __nv_bfloat16* hjIr = hjs + ii*HP;
            char* rowBlo = HtB + (ii*16 + jlo)*PH;
            char* rowBhi = HtB + (ii*16 + jhi)*PH;
            #pragma unroll
            for (int nt = 0; nt < 19; nt++) {
                int col = nt*8 + (lane & 3)*2;
                float2 hiI = bf2_to_f2(*(const uint32_t*)(hiIr + col));
                float2 hjl = bf2_to_f2(*(const uint32_t*)(hjJl + col));
                float2 hjh = bf2_to_f2(*(const uint32_t*)(hjJh + col));
                hA[mt][nt][0] = pack_bf2(fmaxf(acc[mt][nt][0] + hiI.x + hjl.x, 0.f),
                                         fmaxf(acc[mt][nt][1] + hiI.y + hjl.y, 0.f));
                hA[mt][nt][1] = pack_bf2(fmaxf(acc[mt][nt][2] + hiI.x + hjh.x, 0.f),
                                         fmaxf(acc[mt][nt][3] + hiI.y + hjh.y, 0.f));
                if (!diag) {
                    float2 hjI = bf2_to_f2(*(const uint32_t*)(hjIr + col));
                    float2 hil = bf2_to_f2(*(const uint32_t*)(hiJl + col));
                    float2 hih = bf2_to_f2(*(const uint32_t*)(hiJh + col));
                    *(uint32_t*)(rowBlo + col*2) =
                        pack_bf2(fmaxf(acc[mt][nt][0] + hil.x + hjI.x, 0.f),
                                 fmaxf(acc[mt][nt][1] + hil.y + hjI.y, 0.f));
                    *(uint32_t*)(rowBhi + col*2) =
                        pack_bf2(fmaxf(acc[mt][nt][2] + hih.x + hjI.x, 0.f),
                                 fmaxf(acc[mt][nt][3] + hih.y + hjI.y, 0.f));
                }
            }
        }
    }
    __syncthreads();   // W2s + HtB ready

    // ---- stage 2 ----
    const uint32_t W2a  = smem_u32(W2s);
    const uint32_t HtBa = smem_u32(HtB);
    const float b3v = b3[0];

    auto stage2 = [&](bool useHtB, int pass) {
        float sl[2] = {0.f, 0.f}, sh[2] = {0.f, 0.f};
        #pragma unroll
        for (int hf = 0; hf < 2; hf++) {
            float a2c[2][10][4];
            #pragma unroll
            for (int mt = 0; mt < 2; mt++)
                #pragma unroll
                for (int n = 0; n < 10; n++)
                    #pragma unroll
                    for (int k = 0; k < 4; k++) a2c[mt][n][k] = 0.f;

            #pragma unroll
            for (int ks = 0; ks < 9; ks++) {
                uint32_t a0[2], a1[2], a2[2], a3[2];
                #pragma unroll
                for (int mt = 0; mt < 2; mt++) {
                    if (useHtB) {
                        uint32_t ab = HtBa + ((w + 8*mt)*16 + (lane & 15))*PH
                                    + ((lane >> 4) << 4) + ks*32;
                        ldsm_x4(a0[mt], a1[mt], a2[mt], a3[mt], ab);
                    } else {
                        a0[mt] = hA[mt][2*ks][0];     a1[mt] = hA[mt][2*ks][1];
                        a2[mt] = hA[mt][2*ks + 1][0]; a3[mt] = hA[mt][2*ks + 1][1];
                    }
                }
                if (hf == 0) {
                    uint32_t bb = W2a + brow*PH + bkoff + ks*32;
                    #pragma unroll
                    for (int np = 0; np < 5; np++) {
                        uint32_t b0, b1r, b2r, b3r;
                        ldsm_x4(b0, b1r, b2r, b3r, bb + np*(16*PH));
                        mma16816(a2c[0][2*np],     a0[0], a1[0], a2[0], a3[0], b0, b1r);
                        mma16816(a2c[1][2*np],     a0[1], a1[1], a2[1], a3[1], b0, b1r);
                        mma16816(a2c[0][2*np + 1], a0[0], a1[0], a2[0], a3[0], b2r, b3r);
                        mma16816(a2c[1][2*np + 1], a0[1], a1[1], a2[1], a3[1], b2r, b3r);
                    }
                } else {
                    uint32_t bb = W2a + (80 + brow)*PH + bkoff + ks*32;
                    #pragma unroll
                    for (int np = 0; np < 4; np++) {
                        uint32_t b0, b1r, b2r, b3r;
                        ldsm_x4(b0, b1r, b2r, b3r, bb + np*(16*PH));
                        mma16816(a2c[0][2*np],     a0[0], a1[0], a2[0], a3[0], b0, b1r);
                        mma16816(a2c[1][2*np],     a0[1], a1[1], a2[1], a3[1], b0, b1r);
                        mma16816(a2c[0][2*np + 1], a0[0], a1[0], a2[0], a3[0], b2r, b3r);
                        mma16816(a2c[1][2*np + 1], a0[1], a1[1], a2[1], a3[1], b2r, b3r);
                    }
                    uint32_t b0, b1r;
                    ldsm_x2(b0, b1r, W2a + (144 + (lane & 7))*PH + bkoff + ks*32);
                    mma16816(a2c[0][8], a0[0], a1[0], a2[0], a3[0], b0, b1r);
                    mma16816(a2c[1][8], a0[1], a1[1], a2[1], a3[1], b0, b1r);
                }
            }
            {   // k8 tail (cols 144-151, byte 288)
                uint32_t ta[2], tb[2];
                #pragma unroll
                for (int mt = 0; mt < 2; mt++) {
                    if (useHtB) {
                        ldsm_x2(ta[mt], tb[mt],
                                HtBa + ((w + 8*mt)*16 + (lane & 15))*PH + 288);
                    } else {
                        ta[mt] = hA[mt][18][0]; tb[mt] = hA[mt][18][1];
                    }
                }
                if (hf == 0) {
                    #pragma unroll
                    for (int q = 0; q < 2; q++) {
                        uint32_t b0, b1r, b2r, b3r;
                        ldsm_x4(b0, b1r, b2r, b3r,
                                W2a + (uint32_t)((q*32 + (lane >> 3)*8 + (lane & 7))*PH + 288));
                        #pragma unroll
                        for (int mt = 0; mt < 2; mt++) {
                            mma16808(a2c[mt][4*q + 0], ta[mt], tb[mt], b0);
                            mma16808(a2c[mt][4*q + 1], ta[mt], tb[mt], b1r);
                            mma16808(a2c[mt][4*q + 2], ta[mt], tb[mt], b2r);
                            mma16808(a2c[mt][4*q + 3], ta[mt], tb[mt], b3r);
                        }
                    }
                    uint32_t b0, b1r;
                    ldsm_x2(b0, b1r,
                            W2a + (uint32_t)((64 + ((lane >> 3) & 1)*8 + (lane & 7))*PH + 288));
                    #pragma unroll
                    for (int mt = 0; mt < 2; mt++) {
                        mma16808(a2c[mt][8], ta[mt], tb[mt], b0);
                        mma16808(a2c[mt][9], ta[mt], tb[mt], b1r);
                    }
                } else {
                    #pragma unroll
                    for (int q = 0; q < 2; q++) {
                        uint32_t b0, b1r, b2r, b3r;
                        ldsm_x4(b0, b1r, b2r, b3r,
                                W2a + (uint32_t)((80 + q*32 + (lane >> 3)*8 + (lane & 7))*PH + 288));
                        #pragma unroll
                        for (int mt = 0; mt < 2; mt++) {
                            mma16808(a2c[mt][4*q + 0], ta[mt], tb[mt], b0);
                            mma16808(a2c[mt][4*q + 1], ta[mt], tb[mt], b1r);
                            mma16808(a2c[mt][4*q + 2], ta[mt], tb[mt], b2r);
                            mma16808(a2c[mt][4*q + 3], ta[mt], tb[mt], b3r);
                        }
                    }
                    uint32_t bx;
                    ldsm_x1(bx, W2a + (uint32_t)((144 + (lane & 7))*PH + 288));
                    #pragma unroll
                    for (int mt = 0; mt < 2; mt++)
                        mma16808(a2c[mt][8], ta[mt], tb[mt], bx);
                }
            }
            const int ntl = hf ? 9 : 10;
            #pragma unroll
            for (int mt = 0; mt < 2; mt++) {
                #pragma unroll
                for (int nt = 0; nt < 10; nt++) {
                    if (nt >= ntl) break;
                    int col = hf*80 + nt*8 + (lane & 3)*2;
                    sl[mt] = fmaf(fmaxf(a2c[mt][nt][0] + b2s[col],     0.f), w3s[col],     sl[mt]);
                    sl[mt] = fmaf(fmaxf(a2c[mt][nt][1] + b2s[col + 1], 0.f), w3s[col + 1], sl[mt]);
                    sh[mt] = fmaf(fmaxf(a2c[mt][nt][2] + b2s[col],     0.f), w3s[col],     sh[mt]);
                    sh[mt] = fmaf(fmaxf(a2c[mt][nt][3] + b2s[col + 1], 0.f), w3s[col + 1], sh[mt]);
                }
            }
        }
        #pragma unroll
        for (int mt = 0; mt < 2; mt++) {
            sl[mt] += __shfl_xor_sync(0xFFFFFFFF, sl[mt], 1);
            sl[mt] += __shfl_xor_sync(0xFFFFFFFF, sl[mt], 2);
            sh[mt] += __shfl_xor_sync(0xFFFFFFFF, sh[mt], 1);
            sh[mt] += __shfl_xor_sync(0xFFFFFFFF, sh[mt], 2);
        }
        if ((lane & 3) == 0) {
            int jlo = lane >> 2, jhi = jlo + 8;
            #pragma unroll
            for (int mt = 0; mt < 2; mt++) {
                int ii = w + 8*mt;
                float rl = (mIs[ii] + mJs[jlo] + sl[mt] + b3v) * (1.0f/3.0f);
                float rh = (mIs[ii] + mJs[jhi] + sh[mt] + b3v) * (1.0f/3.0f);
                if (pass == 0) {
                    out[(size_t)(b*NQ + i0 + ii)*NQ + j0 + jlo] = rl;
                    out[(size_t)(b*NQ + i0 + ii)*NQ + j0 + jhi] = rh;
                } else {
                    out[(size_t)(b*NQ + j0 + jlo)*NQ + i0 + ii] = rl;
                    out[(size_t)(b*NQ + j0 + jhi)*NQ + i0 + ii] = rh;
                }
            }
        }
    };

    stage2(false, 0);
    if (!diag) {
        __syncwarp();
        stage2(true, 1);
    }
}

// ---------------------------------------------------------------------------
extern "C" void kernel_launch(void* const* d_in, const int* in_sizes, int n_in,
                              void* d_out, int out_size) {
    const float* g  = (const float*)d_in[0];
    const float* m  = (const float*)d_in[1];
    const float* W1 = (const float*)d_in[2];
    const float* b1 = (const float*)d_in[3];
    const float* W2 = (const float*)d_in[4];
    const float* b2 = (const float*)d_in[5];
    const float* W3 = (const float*)d_in[6];
    const float* b3 = (const float*)d_in[7];
    float* out = (float*)d_out;

    cudaFuncSetAttribute(pair_frag2_kernel,
                         cudaFuncAttributeMaxDynamicSharedMemorySize, SMEM_BYTES);

    prep_w1ct<<<dim3(ED/32, 5), dim3(32, 32)>>>(W1);
    prep_w2t<<<HP, HP>>>(W2);
    prep_hihj<<<dim3(NQ/8, BB, 2), dim3(160, 4)>>>(g, W1, b1);
    pair_frag2_kernel<<<dim3(136, BB), 256, SMEM_BYTES>>>(g, m, b2, W3, b3, out);
}